// round 4
// baseline (speedup 1.0000x reference)
#include <cuda_runtime.h>
#include <cstdint>

#define TT 512      // time steps
#define NB 512      // batch
#define CC 80       // classes
#define SS 128      // max target len
#define LL 257      // extended lattice = 2*SS+1
#define CELLS 9     // lattice cells per lane (32*9=288 >= 257)
#define WPB 4       // warps (batch elems) per block
#define RD 8        // cp.async ring depth (steps)

__device__ __forceinline__ unsigned smem_u32(const void* p) {
    return (unsigned)__cvta_generic_to_shared(p);
}
__device__ __forceinline__ void cp16(unsigned dst, const float* src) {
    asm volatile("cp.async.cg.shared.global [%0], [%1], 16;\n"
                 :: "r"(dst), "l"(__cvta_generic_to_global(src)) : "memory");
}
__device__ __forceinline__ void cp_commit() {
    asm volatile("cp.async.commit_group;\n" ::: "memory");
}
template <int N> __device__ __forceinline__ void cp_wait() {
    asm volatile("cp.async.wait_group %0;\n" :: "n"(N) : "memory");
}
// exact power of two 2^e with exponent clamped to representable normals
__device__ __forceinline__ float exp2c(int e) {
    e = max(-126, min(127, e));
    return __int_as_float((e + 127) << 23);
}

__global__ __launch_bounds__(WPB * 32)
void ctc_kernel(const float* __restrict__ lp,   // (T, N, C)
                const int*   __restrict__ tgt,  // (N, S)
                const int*   __restrict__ ilen, // (N,)
                const int*   __restrict__ tlen, // (N,)
                float*       __restrict__ out,  // (N,)
                int nb)
{
    __shared__ __align__(16) float raw[WPB][RD][CC]; // ring of raw log-prob rows
    __shared__ __align__(16) float em[WPB][2][84];   // double-buffered exp'd probs (+pad slot 80)
    __shared__ int ed[WPB][32];                      // per-lane exponents at finalize

    const int lane = threadIdx.x & 31;
    const int w    = threadIdx.x >> 5;
    const int n    = blockIdx.x * WPB + w;
    if (n >= nb) return;

    const int Tn = ilen[n];
    const int tl = tlen[n];

    if (lane == 0) { em[w][0][80] = 0.f; em[w][1][80] = 0.f; } // pad class -> prob 0

    // ---- per-cell static setup: class index + skip multiplier ----
    float alpha[CELLS];
    int   cls[CELLS];
    float skf[CELLS];
    const int* trow = tgt + (size_t)n * SS;
    #pragma unroll
    for (int j = 0; j < CELLS; j++) {
        int s = lane * CELLS + j;
        alpha[j] = 0.f;
        if (s >= LL)            { cls[j] = 80; skf[j] = 0.f; }
        else if ((s & 1) == 0)  { cls[j] = 0;  skf[j] = 0.f; }      // blank
        else {
            int k = s >> 1;                 // label index for odd s
            int c = trow[k];
            cls[j] = c;
            skf[j] = (k >= 1 && trow[k - 1] != c) ? 1.f : 0.f;
        }
    }

    const float* gbase = lp + (size_t)n * CC;   // + t * (NB*CC)

    // ---- pipeline prologue: fill cp.async ring with rows 0..RD-1 ----
    #pragma unroll
    for (int d = 0; d < RD; d++) {
        if (lane < 20)
            cp16(smem_u32(&raw[w][d][lane * 4]),
                 gbase + (size_t)d * (NB * CC) + lane * 4);
        cp_commit();
    }
    cp_wait<RD - 1>();
    __syncwarp();
    if (lane < 20) {                            // process row 0 -> em buf 0
        float4 r = *(const float4*)&raw[w][0][lane * 4];
        float4 p;
        p.x = __expf(r.x); p.y = __expf(r.y); p.z = __expf(r.z); p.w = __expf(r.w);
        *(float4*)&em[w][0][lane * 4] = p;
    }
    __syncwarp();
    // alpha at t=0: only lattice positions 0 (blank) and 1 (first label)
    if (lane == 0) {
        alpha[0] = em[w][0][0];
        alpha[1] = em[w][0][cls[1]];
    }
    cp_wait<RD - 2>();
    __syncwarp();
    if (lane < 20) {                            // process row 1 -> em buf 1
        float4 r = *(const float4*)&raw[w][1][lane * 4];
        float4 p;
        p.x = __expf(r.x); p.y = __expf(r.y); p.z = __expf(r.z); p.w = __expf(r.w);
        *(float4*)&em[w][1][lane * 4] = p;
    }
    __syncwarp();

    // ---- per-lane block-floating-point state ----
    int  elane = 0;                 // true alpha = stored * 2^elane (per lane)
    bool empty = (lane != 0);       // lane has no probability mass yet

    for (int t = 1; t < Tn; t++) {
        const float* emc = &em[w][t & 1][0];

        // hoisted emission gathers (class indices are loop-invariant)
        float g0 = emc[cls[0]], g1 = emc[cls[1]], g2 = emc[cls[2]];
        float g3 = emc[cls[3]], g4 = emc[cls[4]], g5 = emc[cls[5]];
        float g6 = emc[cls[6]], g7 = emc[cls[7]], g8 = emc[cls[8]];

        // lane-boundary values (old alpha from lane-1), with exponent alignment
        float p8 = __shfl_up_sync(0xffffffffu, alpha[CELLS - 1], 1);
        float p7 = __shfl_up_sync(0xffffffffu, alpha[CELLS - 2], 1);
        int eprev = __shfl_up_sync(0xffffffffu, elane, 1);
        int de = eprev - elane;
        if (lane == 0) { p8 = 0.f; p7 = 0.f; de = 0; }

        // rebase this lane to the neighbor's exponent if we're empty or
        // the neighbor dominates by >2^100 (own mass then negligible forever)
        if (empty || de > 100) {
            float g = exp2c(-de);
            #pragma unroll
            for (int j = 0; j < CELLS; j++) alpha[j] *= g;
            elane += de;            // elane = eprev
            de = 0;
        }
        float f = exp2c(de);        // de <= 100 here; very negative -> ~0
        p8 *= f; p7 *= f;

        // update descending so in-place reads see old values
        { float a = alpha[8] + alpha[7]; a = fmaf(alpha[6], skf[8], a); alpha[8] = a * g8; }
        { float a = alpha[7] + alpha[6]; a = fmaf(alpha[5], skf[7], a); alpha[7] = a * g7; }
        { float a = alpha[6] + alpha[5]; a = fmaf(alpha[4], skf[6], a); alpha[6] = a * g6; }
        { float a = alpha[5] + alpha[4]; a = fmaf(alpha[3], skf[5], a); alpha[5] = a * g5; }
        { float a = alpha[4] + alpha[3]; a = fmaf(alpha[2], skf[4], a); alpha[4] = a * g4; }
        { float a = alpha[3] + alpha[2]; a = fmaf(alpha[1], skf[3], a); alpha[3] = a * g3; }
        { float a = alpha[2] + alpha[1]; a = fmaf(alpha[0], skf[2], a); alpha[2] = a * g2; }
        { float a = alpha[1] + alpha[0]; a = fmaf(p8,       skf[1], a); alpha[1] = a * g1; }
        { float a = alpha[0] + p8;       a = fmaf(p7,       skf[0], a); alpha[0] = a * g0; }

        // prefetch row t+RD-1
        {
            int ttu = t + RD - 1;
            if (lane < 20 && ttu < TT)
                cp16(smem_u32(&raw[w][ttu & (RD - 1)][lane * 4]),
                     gbase + (size_t)ttu * (NB * CC) + lane * 4);
            cp_commit();
        }
        cp_wait<RD - 2>();
        // process row t+1 into the other em buffer
        {
            int tn1 = t + 1;
            if (lane < 20) {
                float4 r = *(const float4*)&raw[w][tn1 & (RD - 1)][lane * 4];
                float4 p;
                p.x = __expf(r.x); p.y = __expf(r.y); p.z = __expf(r.z); p.w = __expf(r.w);
                *(float4*)&em[w][tn1 & 1][lane * 4] = p;
            }
        }
        __syncwarp();

        // ---- per-lane power-of-2 rescale (no warp reduction needed) ----
        float m = fmaxf(fmaxf(fmaxf(alpha[0], alpha[1]), fmaxf(alpha[2], alpha[3])),
                        fmaxf(fmaxf(alpha[4], alpha[5]),
                              fmaxf(fmaxf(alpha[6], alpha[7]), alpha[8])));
        if (m > 0.f) {
            int e = ((__float_as_int(m) >> 23) & 255) - 127;
            float sc = exp2c(-e);   // bring lane max into ~[1,2)
            #pragma unroll
            for (int j = 0; j < CELLS; j++) alpha[j] *= sc;
            elane += e;
            empty = false;
        } else {
            empty = true;
        }
    }

    // ---- finalize: combine alpha[2*tl] + alpha[2*tl-1] with per-lane exponents ----
    cp_wait<0>();      // drain ring before reusing its smem
    __syncwarp();
    float* dump = &raw[w][0][0];   // 288 floats fit in the 640-float ring
    #pragma unroll
    for (int j = 0; j < CELLS; j++)
        dump[lane * CELLS + j] = alpha[j];
    ed[w][lane] = elane;
    __syncwarp();
    if (lane == 0) {
        int s1 = 2 * tl, s2 = 2 * tl - 1;
        float a = dump[s1]; int ea = ed[w][s1 / CELLS];
        float b = dump[s2]; int eb = ed[w][s2 / CELLS];
        int emax = max(ea, eb);
        float v = a * exp2c(ea - emax) + b * exp2c(eb - emax);
        float loss = -((__log2f(v) + (float)emax) * 0.69314718055994530942f);
        if (!isfinite(loss) || !(loss < 1e10f)) loss = 0.f;  // zero_infinity
        out[n] = loss;
    }
}

extern "C" void kernel_launch(void* const* d_in, const int* in_sizes, int n_in,
                              void* d_out, int out_size) {
    const float* lp   = (const float*)d_in[0];
    const int*   tgt  = (const int*)d_in[1];
    const int*   ilen = (const int*)d_in[2];
    const int*   tlen = (const int*)d_in[3];
    float*       out  = (float*)d_out;
    int nb = out_size;                 // N
    int blocks = (nb + WPB - 1) / WPB; // 128
    ctc_kernel<<<blocks, WPB * 32>>>(lp, tgt, ilen, tlen, out, nb);
}

// round 7
// speedup vs baseline: 1.3425x; 1.3425x over previous
#include <cuda_runtime.h>
#include <cstdint>

#define TT 512      // time steps
#define NB 512      // batch
#define CC 80       // classes
#define SS 128      // max target len
#define LL 257      // extended lattice = 2*SS+1
#define WPB 4       // warps (batch elems) per block
#define RD 8        // cp.async ring depth (rows)
#define NBC (NB*CC) // row stride in floats

static __device__ __forceinline__ unsigned smem_u32(const void* p) {
    return (unsigned)__cvta_generic_to_shared(p);
}
static __device__ __forceinline__ void cp16(unsigned dst, const float* src) {
    asm volatile("cp.async.cg.shared.global [%0], [%1], 16;\n"
                 :: "r"(dst), "l"(__cvta_generic_to_global(src)) : "memory");
}
static __device__ __forceinline__ void cp_commit() {
    asm volatile("cp.async.commit_group;\n" ::: "memory");
}
template <int N> static __device__ __forceinline__ void cp_wait() {
    asm volatile("cp.async.wait_group %0;\n" :: "n"(N) : "memory");
}
// exact power of two 2^e, exponent clamped to normal range
static __device__ __forceinline__ float exp2c(int e) {
    e = max(-126, min(127, e));
    return __int_as_float((e + 127) << 23);
}

struct WState {
    float a[9];     // alpha cells (lattice s = lane*9 + j)
    float sk[9];    // skip-transition multiplier (0/1)
    int   co[9];    // emission byte offset = class*4
    float p8r, p7r; // pre-rescale boundary alphas shfl'd from lane-1
    int   elane;    // per-lane exponent: true alpha = a * 2^elane
    int   eprev;    // lane-1's elane at shfl time
    bool  empty;    // lane has no probability mass yet
};

template <int BUF, bool RESC>
static __device__ __forceinline__ void ctc_step(
    WState& S, int tcur, int lane,
    float (&rawW)[RD][CC], float (&emW)[2][84], const float*& gpre)
{
    // emission gathers (depend only on em buffer written last step)
    const char* emc = (const char*)&emW[BUF][0];
    float g[9];
#pragma unroll
    for (int j = 0; j < 9; j++)
        g[j] = *(const float*)(emc + S.co[j]);

    // exponent alignment with left neighbor
    int de = S.eprev - S.elane;
    if (S.empty) { S.elane = S.eprev; de = 0; }        // alpha==0: adopt, no mults
    else if (de > 100) {                               // ~never taken
        if (de > 252) {
#pragma unroll
            for (int j = 0; j < 9; j++) S.a[j] = 0.f;
        } else {
            float r1 = exp2c(-(de >> 1)), r2 = exp2c(-(de - (de >> 1)));
#pragma unroll
            for (int j = 0; j < 9; j++) S.a[j] = (S.a[j] * r1) * r2;
        }
        S.elane += de; de = 0;
    }
    float f  = exp2c(de);
    float p8 = S.p8r * f, p7 = S.p7r * f;

    // cell updates, descending so in-place reads see old values
#pragma unroll
    for (int j = 8; j >= 2; j--) {
        float tv = S.a[j] + S.a[j - 1];
        tv = fmaf(S.a[j - 2], S.sk[j], tv);
        S.a[j] = tv * g[j];
    }
    { float tv = S.a[1] + S.a[0]; tv = fmaf(p8, S.sk[1], tv); S.a[1] = tv * g[1]; }
    { float tv = S.a[0] + p8;     tv = fmaf(p7, S.sk[0], tv); S.a[0] = tv * g[0]; }

    if (p8 > 0.f) S.empty = false;   // mass injected from the left

    // early shfl for NEXT step (pre-rescale values + current exponent)
    S.p8r   = __shfl_up_sync(0xffffffffu, S.a[8], 1);
    S.p7r   = __shfl_up_sync(0xffffffffu, S.a[7], 1);
    S.eprev = __shfl_up_sync(0xffffffffu, S.elane, 1);
    if (lane == 0) { S.p8r = 0.f; S.p7r = 0.f; S.eprev = S.elane; }

    // prefetch row tcur+RD-1 into the ring
    {
        int ttu = tcur + RD - 1;
        if (lane < 20 && ttu < TT)
            cp16(smem_u32(&rawW[ttu & (RD - 1)][lane * 4]), gpre + lane * 4);
        cp_commit();
        gpre += NBC;
    }
    cp_wait<RD - 2>();
    // exp-convert row tcur+1 into the other em buffer
    if (lane < 20) {
        float4 r = *(const float4*)&rawW[(tcur + 1) & (RD - 1)][lane * 4];
        float4 p;
        p.x = __expf(r.x); p.y = __expf(r.y); p.z = __expf(r.z); p.w = __expf(r.w);
        *(float4*)&emW[(tcur + 1) & 1][lane * 4] = p;
    }
    __syncwarp();

    if (RESC) {   // per-lane power-of-2 renormalization (every 2nd step)
        float m = fmaxf(fmaxf(fmaxf(S.a[0], S.a[1]), fmaxf(S.a[2], S.a[3])),
                        fmaxf(fmaxf(S.a[4], S.a[5]),
                              fmaxf(fmaxf(S.a[6], S.a[7]), S.a[8])));
        if (m > 0.f) {
            int e = ((__float_as_int(m) >> 23) & 255) - 127;
            float sc = exp2c(-e);
#pragma unroll
            for (int j = 0; j < 9; j++) S.a[j] *= sc;
            S.elane += e;
            S.empty = false;
        } else {
            S.empty = true;
        }
    }
}

__global__ __launch_bounds__(WPB * 32)
void ctc_kernel(const float* __restrict__ lp,   // (T, N, C)
                const int*   __restrict__ tgt,  // (N, S)
                const int*   __restrict__ ilen, // (N,)
                const int*   __restrict__ tlen, // (N,)
                float*       __restrict__ out,  // (N,)
                int nb)
{
    __shared__ __align__(16) float raw[WPB][RD][CC]; // ring of raw log-prob rows
    __shared__ __align__(16) float em[WPB][2][84];   // double-buffered exp'd probs
    __shared__ int ed[WPB][32];                      // per-lane exponents at finalize

    const int lane = threadIdx.x & 31;
    const int w    = threadIdx.x >> 5;
    const int n    = blockIdx.x * WPB + w;
    if (n >= nb) return;

    float (&rawW)[RD][CC] = raw[w];
    float (&emW)[2][84]   = em[w];

    const int Tn = ilen[n];
    const int tl = tlen[n];

    if (lane == 0) { emW[0][80] = 0.f; emW[1][80] = 0.f; } // pad class -> prob 0

    WState S;
    const int* trow = tgt + (size_t)n * SS;
#pragma unroll
    for (int j = 0; j < 9; j++) {
        int s = lane * 9 + j;
        S.a[j] = 0.f;
        if (s >= LL)            { S.co[j] = 80 * 4; S.sk[j] = 0.f; }
        else if ((s & 1) == 0)  { S.co[j] = 0;      S.sk[j] = 0.f; }   // blank
        else {
            int k = s >> 1;
            int c = trow[k];
            S.co[j] = c * 4;
            S.sk[j] = (k >= 1 && trow[k - 1] != c) ? 1.f : 0.f;
        }
    }

    const float* gbase = lp + (size_t)n * CC;

    // ---- prologue: fill ring with rows 0..7 ----
#pragma unroll
    for (int d = 0; d < RD; d++) {
        if (lane < 20)
            cp16(smem_u32(&rawW[d][lane * 4]),
                 gbase + (size_t)d * NBC + lane * 4);
        cp_commit();
    }
    cp_wait<RD - 2>();   // rows 0,1 landed
    __syncwarp();
    if (lane < 20) {
        float4 r0 = *(const float4*)&rawW[0][lane * 4];
        float4 p0;
        p0.x = __expf(r0.x); p0.y = __expf(r0.y); p0.z = __expf(r0.z); p0.w = __expf(r0.w);
        *(float4*)&emW[0][lane * 4] = p0;
        float4 r1 = *(const float4*)&rawW[1][lane * 4];
        float4 p1;
        p1.x = __expf(r1.x); p1.y = __expf(r1.y); p1.z = __expf(r1.z); p1.w = __expf(r1.w);
        *(float4*)&emW[1][lane * 4] = p1;
    }
    __syncwarp();

    // alpha at t=0: only lattice positions 0 (blank) and 1 (first label)
    if (lane == 0) {
        S.a[0] = *(const float*)((const char*)&emW[0][0] + 0);
        S.a[1] = *(const float*)((const char*)&emW[0][0] + S.co[1]);
    }
    S.elane = 0;
    S.empty = (lane != 0);

    // initial boundary shfl (pre-rescale values at t=0)
    S.p8r   = __shfl_up_sync(0xffffffffu, S.a[8], 1);
    S.p7r   = __shfl_up_sync(0xffffffffu, S.a[7], 1);
    S.eprev = __shfl_up_sync(0xffffffffu, S.elane, 1);
    if (lane == 0) { S.p8r = 0.f; S.p7r = 0.f; S.eprev = S.elane; }

    const float* gpre = gbase + (size_t)RD * NBC;   // row 8 (first in-loop prefetch)

    // ---- main loop: steps 1 .. Tn-1, unrolled by 2 ----
    int t = 1;
    for (; t + 1 < Tn; t += 2) {
        ctc_step<1, false>(S, t,     lane, rawW, emW, gpre);
        ctc_step<0, true >(S, t + 1, lane, rawW, emW, gpre);
    }
    if (t < Tn)
        ctc_step<1, true>(S, t, lane, rawW, emW, gpre);

    // ---- finalize: combine alpha[2*tl] + alpha[2*tl-1] with per-lane exponents ----
    cp_wait<0>();
    __syncwarp();
    float* dump = &rawW[0][0];   // 288 floats fit in the 640-float ring
#pragma unroll
    for (int j = 0; j < 9; j++)
        dump[lane * 9 + j] = S.a[j];
    ed[w][lane] = S.elane;
    __syncwarp();
    if (lane == 0) {
        int s1 = 2 * tl, s2 = 2 * tl - 1;
        float va = dump[s1]; int ea = ed[w][s1 / 9];
        float vb = dump[s2]; int eb = ed[w][s2 / 9];
        int emax = max(ea, eb);
        float v = va * exp2c(ea - emax) + vb * exp2c(eb - emax);
        float loss = -((__log2f(v) + (float)emax) * 0.69314718055994530942f);
        if (!isfinite(loss) || !(loss < 1e10f)) loss = 0.f;  // zero_infinity
        out[n] = loss;
    }
}

extern "C" void kernel_launch(void* const* d_in, const int* in_sizes, int n_in,
                              void* d_out, int out_size) {
    const float* lp   = (const float*)d_in[0];
    const int*   tgt  = (const int*)d_in[1];
    const int*   ilen = (const int*)d_in[2];
    const int*   tlen = (const int*)d_in[3];
    float*       out  = (float*)d_out;
    int nb = out_size;                 // N
    int blocks = (nb + WPB - 1) / WPB; // 128
    ctc_kernel<<<blocks, WPB * 32>>>(lp, tgt, ilen, tlen, out, nb);
}